// round 15
// baseline (speedup 1.0000x reference)
#include <cuda_runtime.h>
#include <cuda_bf16.h>
#include <cstdint>

#define BATCH 4
#define C_IN 256
#define C_MID 128
#define NSP 4096
#define INVN (1.0f/4096.0f)
#define GRIDN 288

typedef __nv_bfloat16 bf16;
typedef __nv_bfloat162 bf162;

// ---------------------------------------------------------------------------
// Device scratch
// ---------------------------------------------------------------------------
__device__ __align__(256) bf16  d_Xbf[BATCH * C_IN * NSP];
__device__ __align__(256) bf16  d_phw[C_MID * C_IN];
__device__ __align__(256) bf16  d_gw [C_MID * C_IN];
__device__ __align__(256) bf16  d_thw[C_MID * C_IN];
__device__ __align__(256) bf16  d_ow [C_IN * C_MID];
__device__ __align__(256) bf16  d_Tph[BATCH * C_MID * NSP];
__device__ __align__(256) bf16  d_Tg [BATCH * C_MID * NSP];
__device__ __align__(256) float d_M  [BATCH * C_MID * C_MID];
__device__ __align__(256) float d_gs [BATCH * C_MID];
__device__ __align__(256) float d_ws [BATCH * C_MID];
__device__ __align__(256) float d_W  [BATCH * C_IN * C_MID];
__device__ __align__(256) bf16  d_Af [BATCH * C_IN * C_IN];
__device__ __align__(256) float d_cvec[BATCH * C_IN];
__device__ unsigned int g_bc[8];      // barrier counters (monotonic)

// ---------------------------------------------------------------------------
// Helpers
// ---------------------------------------------------------------------------
__device__ __forceinline__ void mma_bf16(float c[4], const uint32_t a[4],
                                         uint32_t b0, uint32_t b1) {
    asm volatile("mma.sync.aligned.m16n8k16.row.col.f32.bf16.bf16.f32 "
                 "{%0,%1,%2,%3}, {%4,%5,%6,%7}, {%8,%9}, {%0,%1,%2,%3};"
                 : "+f"(c[0]), "+f"(c[1]), "+f"(c[2]), "+f"(c[3])
                 : "r"(a[0]), "r"(a[1]), "r"(a[2]), "r"(a[3]), "r"(b0), "r"(b1));
}
__device__ __forceinline__ void ldsm4(uint32_t r[4], const bf16* p) {
    uint32_t addr = (uint32_t)__cvta_generic_to_shared(p);
    asm volatile("ldmatrix.sync.aligned.m8n8.x4.shared.b16 {%0,%1,%2,%3}, [%4];"
                 : "=r"(r[0]), "=r"(r[1]), "=r"(r[2]), "=r"(r[3]) : "r"(addr));
}
__device__ __forceinline__ void ldsm4t(uint32_t r[4], const bf16* p) {
    uint32_t addr = (uint32_t)__cvta_generic_to_shared(p);
    asm volatile("ldmatrix.sync.aligned.m8n8.x4.trans.shared.b16 {%0,%1,%2,%3}, [%4];"
                 : "=r"(r[0]), "=r"(r[1]), "=r"(r[2]), "=r"(r[3]) : "r"(addr));
}
__device__ __forceinline__ void cp16(bf16* s, const bf16* g) {
    uint32_t sa = (uint32_t)__cvta_generic_to_shared(s);
    asm volatile("cp.async.cg.shared.global [%0], [%1], 16;" :: "r"(sa), "l"(g));
}
#define CP_COMMIT() asm volatile("cp.async.commit_group;" ::: "memory")
#define CP_WAIT1()  asm volatile("cp.async.wait_group 1;" ::: "memory")
#define CP_WAIT0()  asm volatile("cp.async.wait_group 0;" ::: "memory")

__device__ __forceinline__ uint2 f4_to_bf(float4 v) {
    bf162 lo = __floats2bfloat162_rn(v.x, v.y);
    bf162 hi = __floats2bfloat162_rn(v.z, v.w);
    uint2 r;
    r.x = *(uint32_t*)&lo;
    r.y = *(uint32_t*)&hi;
    return r;
}
__device__ __forceinline__ float sum8bf(uint4 v) {
    const bf162* p = (const bf162*)&v;
    float s = 0.f;
#pragma unroll
    for (int i = 0; i < 4; i++) {
        float2 f = __bfloat1622float2(p[i]);
        s += f.x + f.y;
    }
    return s;
}

// epoch-based grid barrier (monotonic counter; safe across graph replays)
__device__ __forceinline__ void gbar(int i) {
    __syncthreads();
    if (threadIdx.x == 0) {
        __threadfence();
        unsigned old = atomicAdd(&g_bc[i], 1u);
        unsigned goal = (old / GRIDN + 1u) * GRIDN;
        while (atomicAdd(&g_bc[i], 0u) < goal) __nanosleep(64);
        __threadfence();
    }
    __syncthreads();
}

// ---------------------------------------------------------------------------
// Stage bodies
// ---------------------------------------------------------------------------
__device__ void conv_body(int b, const float* __restrict__ x,
                          const float* __restrict__ phi_w,
                          const float* __restrict__ g_w,
                          const float* __restrict__ theta_w,
                          const float* __restrict__ out_w) {
    const int tid = threadIdx.x;
    if (b < 256) {
        const float4* src = (const float4*)x + (size_t)b * 4096;
        uint2* dst = (uint2*)d_Xbf + (size_t)b * 4096;
#pragma unroll 4
        for (int i = tid; i < 4096; i += 256) dst[i] = f4_to_bf(src[i]);
    } else if (b < 264) {
        const float4* src = (const float4*)phi_w + (b - 256) * 1024;
        uint2* dst = (uint2*)d_phw + (b - 256) * 1024;
#pragma unroll
        for (int i = tid; i < 1024; i += 256) dst[i] = f4_to_bf(src[i]);
    } else if (b < 272) {
        const float4* src = (const float4*)g_w + (b - 264) * 1024;
        uint2* dst = (uint2*)d_gw + (b - 264) * 1024;
#pragma unroll
        for (int i = tid; i < 1024; i += 256) dst[i] = f4_to_bf(src[i]);
    } else if (b < 280) {
        const float4* src = (const float4*)theta_w + (b - 272) * 1024;
        uint2* dst = (uint2*)d_thw + (b - 272) * 1024;
#pragma unroll
        for (int i = tid; i < 1024; i += 256) dst[i] = f4_to_bf(src[i]);
    } else if (b < 288) {
        const float4* src = (const float4*)out_w + (b - 280) * 1024;
        uint2* dst = (uint2*)d_ow + (b - 280) * 1024;
#pragma unroll
        for (int i = tid; i < 1024; i += 256) dst[i] = f4_to_bf(src[i]);
    } else if (b < 296) {
        float4* M4 = (float4*)d_M + (b - 288) * 2048;
        float4 z4 = make_float4(0, 0, 0, 0);
#pragma unroll
        for (int i = tid; i < 2048; i += 256) M4[i] = z4;
    } else {
        float4 z4 = make_float4(0, 0, 0, 0);
        if (tid < 128) {
            ((float4*)d_gs)[tid] = z4;
            ((float4*)d_ws)[tid] = z4;
        }
    }
}

__device__ void proj_body(int vx, int vy, int vz, char* smu) {
    bf16* As1 = (bf16*)smu;                    // 3 * 64*40
    bf16* As2 = (bf16*)(smu + 15360);
    bf16* Bs  = (bf16*)(smu + 30720);          // 3 * 32*136
    const int bz = vz;
    const int m0 = vy * 64;
    const int n0 = vx * 128;
    const bf16* Xbf = d_Xbf + (size_t)bz * C_IN * NSP;

    const int tid = threadIdx.x;
    const int lane = tid & 31, warp = tid >> 5;
    const int wm = warp >> 2, wn = warp & 3;
    const int gq = lane >> 2, tg = lane & 3;
    const int ar = tid >> 2, ac = (tid & 3) * 8;
    const int br = tid >> 3, bc = (tid & 7) * 8;
    const int a_row = (lane & 7) + ((lane >> 3) & 1) * 8;
    const int a_col = (lane >> 4) * 8;
    const int bt_kr = (lane & 7) + ((lane >> 3) & 1) * 8;
    const int bt_nc = ((lane >> 4) & 1) * 8;

    float acc1[2][4][4] = {}, acc2[2][4][4] = {};

    auto issue = [&](int k0, int st) {
        cp16(&As1[st * 2560 + ar * 40 + ac], d_phw + (size_t)(m0 + ar) * 256 + k0 + ac);
        cp16(&As2[st * 2560 + ar * 40 + ac], d_gw + (size_t)(m0 + ar) * 256 + k0 + ac);
        cp16(&Bs[st * 4352 + br * 136 + bc], Xbf + (size_t)(k0 + br) * NSP + n0 + bc);
        cp16(&Bs[st * 4352 + br * 136 + bc + 64], Xbf + (size_t)(k0 + br) * NSP + n0 + bc + 64);
    };

    issue(0, 0); CP_COMMIT();
    issue(32, 1); CP_COMMIT();

    for (int i = 0; i < 8; i++) {
        CP_WAIT1();
        __syncthreads();
        int kn = (i + 2) * 32;
        if (kn < 256) issue(kn, (i + 2) % 3);
        CP_COMMIT();
        const int st = i % 3;
#pragma unroll
        for (int kk = 0; kk < 32; kk += 16) {
            uint32_t a1[2][4], a2[2][4], bb[2][4];
#pragma unroll
            for (int ma = 0; ma < 2; ma++) {
                int rb = wm * 32 + ma * 16;
                ldsm4(a1[ma], &As1[st * 2560 + (rb + a_row) * 40 + kk + a_col]);
                ldsm4(a2[ma], &As2[st * 2560 + (rb + a_row) * 40 + kk + a_col]);
            }
#pragma unroll
            for (int pr = 0; pr < 2; pr++)
                ldsm4t(bb[pr], &Bs[st * 4352 + (kk + bt_kr) * 136 + wn * 32 + pr * 16 + bt_nc]);
#pragma unroll
            for (int ma = 0; ma < 2; ma++)
#pragma unroll
                for (int na = 0; na < 4; na++) {
                    uint32_t b0 = bb[na >> 1][(na & 1) * 2];
                    uint32_t b1 = bb[na >> 1][(na & 1) * 2 + 1];
                    mma_bf16(acc1[ma][na], a1[ma], b0, b1);
                    mma_bf16(acc2[ma][na], a2[ma], b0, b1);
                }
        }
    }

    bf16* C1 = d_Tph + (size_t)bz * C_MID * NSP;
    bf16* C2 = d_Tg + (size_t)bz * C_MID * NSP;
#pragma unroll
    for (int ma = 0; ma < 2; ma++) {
        int rm = m0 + wm * 32 + ma * 16 + gq;
#pragma unroll
        for (int na = 0; na < 4; na++) {
            int cn = n0 + wn * 32 + na * 8 + 2 * tg;
            *(bf162*)(C1 + (size_t)rm * NSP + cn) =
                __floats2bfloat162_rn(acc1[ma][na][0], acc1[ma][na][1]);
            *(bf162*)(C1 + (size_t)(rm + 8) * NSP + cn) =
                __floats2bfloat162_rn(acc1[ma][na][2], acc1[ma][na][3]);
            *(bf162*)(C2 + (size_t)rm * NSP + cn) =
                __floats2bfloat162_rn(acc2[ma][na][0], acc2[ma][na][1]);
            *(bf162*)(C2 + (size_t)(rm + 8) * NSP + cn) =
                __floats2bfloat162_rn(acc2[ma][na][2], acc2[ma][na][3]);
        }
    }
    __syncthreads();
}

__device__ void bsm_body(int vx, int vy, int vz, char* smu) {
    bf16* As = (bf16*)smu;                     // 3 * 64*40
    bf16* Bs = (bf16*)(smu + 15360);
    const int ti = vx >> 1, tj = vx & 1;
    const int i0 = ti * 64, j0 = tj * 64;
    const int kb = vy * 512;
    const int bz = vz;
    const bf16* A = d_Tg + (size_t)bz * C_MID * NSP;
    const bf16* B = d_Tph + (size_t)bz * C_MID * NSP;

    const int tid = threadIdx.x;
    const int lane = tid & 31, warp = tid >> 5;
    const int wm = warp >> 2, wn = warp & 3;
    const int gq = lane >> 2, tg = lane & 3;
    const int lr = tid >> 2, lc = (tid & 3) * 8;
    const int a_row = (lane & 7) + ((lane >> 3) & 1) * 8;
    const int a_col = (lane >> 4) * 8;
    const int b_nr = (lane & 7) + ((lane >> 4) & 1) * 8;
    const int b_kc = ((lane >> 3) & 1) * 8;

    float acc[2][2][4] = {};
    float sa = 0.f, sb = 0.f;
    const bool dosum = (ti == tj);

    auto issue = [&](int k0, int st) {
        cp16(&As[st * 2560 + lr * 40 + lc], A + (size_t)(i0 + lr) * NSP + kb + k0 + lc);
        cp16(&Bs[st * 2560 + lr * 40 + lc], B + (size_t)(j0 + lr) * NSP + kb + k0 + lc);
    };

    issue(0, 0); CP_COMMIT();
    issue(32, 1); CP_COMMIT();

    for (int i = 0; i < 16; i++) {
        CP_WAIT1();
        __syncthreads();
        int kn = (i + 2) * 32;
        if (kn < 512) issue(kn, (i + 2) % 3);
        CP_COMMIT();
        const int st = i % 3;
        if (dosum) {
            sa += sum8bf(*(const uint4*)&As[st * 2560 + lr * 40 + lc]);
            sb += sum8bf(*(const uint4*)&Bs[st * 2560 + lr * 40 + lc]);
        }
#pragma unroll
        for (int kk = 0; kk < 32; kk += 16) {
            uint32_t a[2][4], bbv[4];
#pragma unroll
            for (int ma = 0; ma < 2; ma++)
                ldsm4(a[ma], &As[st * 2560 + (wm * 32 + ma * 16 + a_row) * 40 + kk + a_col]);
            ldsm4(bbv, &Bs[st * 2560 + (wn * 16 + b_nr) * 40 + kk + b_kc]);
#pragma unroll
            for (int ma = 0; ma < 2; ma++) {
                mma_bf16(acc[ma][0], a[ma], bbv[0], bbv[1]);
                mma_bf16(acc[ma][1], a[ma], bbv[2], bbv[3]);
            }
        }
    }

    float* Mp = d_M + (size_t)bz * C_MID * C_MID;
#pragma unroll
    for (int ma = 0; ma < 2; ma++) {
        int rr = i0 + wm * 32 + ma * 16 + gq;
#pragma unroll
        for (int na = 0; na < 2; na++) {
            int cn = j0 + wn * 16 + na * 8 + 2 * tg;
            atomicAdd(&Mp[(size_t)rr * C_MID + cn],           acc[ma][na][0]);
            atomicAdd(&Mp[(size_t)rr * C_MID + cn + 1],       acc[ma][na][1]);
            atomicAdd(&Mp[(size_t)(rr + 8) * C_MID + cn],     acc[ma][na][2]);
            atomicAdd(&Mp[(size_t)(rr + 8) * C_MID + cn + 1], acc[ma][na][3]);
        }
    }
    if (dosum) {
        sa += __shfl_xor_sync(0xffffffffu, sa, 1);
        sa += __shfl_xor_sync(0xffffffffu, sa, 2);
        sb += __shfl_xor_sync(0xffffffffu, sb, 1);
        sb += __shfl_xor_sync(0xffffffffu, sb, 2);
        if ((tid & 3) == 0) {
            atomicAdd(&d_gs[bz * C_MID + i0 + lr], sa);
            atomicAdd(&d_ws[bz * C_MID + j0 + lr], sb);
        }
    }
    __syncthreads();
}

__device__ void wfold_body(int vx, int vy, int vz, char* smu,
                           const float* __restrict__ g_b,
                           const float* __restrict__ phi_b) {
    bf16* As = (bf16*)smu;                 // 64*136
    bf16* Bs = (bf16*)(smu + 17408);       // 128*72
    float* pbs = (float*)(smu + 35840);
    float* wss = (float*)(smu + 36352);

    const int bz = vz;
    const int i0 = vy * 64;
    const int j0 = vx * 64;

    const int tid = threadIdx.x;
    const int lane = tid & 31, warp = tid >> 5;
    const int wm = warp >> 2, wn = warp & 3;
    const int gq = lane >> 2, tg = lane & 3;
    const int a_row = (lane & 7) + ((lane >> 3) & 1) * 8;
    const int a_col = (lane >> 4) * 8;
    const int bt_kr = (lane & 7) + ((lane >> 3) & 1) * 8;
    const int bt_nc = ((lane >> 4) & 1) * 8;

    {
        int arow = tid >> 2, acb = (tid & 3) * 32;
#pragma unroll
        for (int i = 0; i < 4; i++)
            cp16(&As[arow * 136 + acb + i * 8],
                 d_ow + (size_t)(i0 + arow) * C_MID + acb + i * 8);
        CP_COMMIT();
    }

    if (tid < 128) {
        pbs[tid] = phi_b[tid];
        wss[tid] = d_ws[bz * C_MID + tid];
    }
    __syncthreads();

    {
        int brow = tid >> 1, bcb = (tid & 1) * 32;
        const float gsv = d_gs[bz * C_MID + brow];
        const float gbv = g_b[brow];
        const float* Mrow = d_M + (size_t)bz * C_MID * C_MID + (size_t)brow * C_MID + j0;
#pragma unroll
        for (int i = 0; i < 8; i++) {
            int c = bcb + i * 4;
            float4 mr = *(const float4*)(Mrow + c);
            float4 pb = *(const float4*)&pbs[j0 + c];
            float4 wv = *(const float4*)&wss[j0 + c];
            float4 v;
            v.x = mr.x + gsv * pb.x + gbv * (wv.x + 4096.f * pb.x);
            v.y = mr.y + gsv * pb.y + gbv * (wv.y + 4096.f * pb.y);
            v.z = mr.z + gsv * pb.z + gbv * (wv.z + 4096.f * pb.z);
            v.w = mr.w + gsv * pb.w + gbv * (wv.w + 4096.f * pb.w);
            *(uint2*)&Bs[brow * 72 + c] = f4_to_bf(v);
        }
    }
    CP_WAIT0();
    __syncthreads();

    float acc[2][2][4] = {};
#pragma unroll
    for (int kk = 0; kk < 128; kk += 16) {
        uint32_t a[2][4], bb[4];
#pragma unroll
        for (int ma = 0; ma < 2; ma++)
            ldsm4(a[ma], &As[(wm * 32 + ma * 16 + a_row) * 136 + kk + a_col]);
        ldsm4t(bb, &Bs[(kk + bt_kr) * 72 + wn * 16 + bt_nc]);
#pragma unroll
        for (int ma = 0; ma < 2; ma++) {
            mma_bf16(acc[ma][0], a[ma], bb[0], bb[1]);
            mma_bf16(acc[ma][1], a[ma], bb[2], bb[3]);
        }
    }

    float* W = d_W + (size_t)bz * C_IN * C_MID;
#pragma unroll
    for (int ma = 0; ma < 2; ma++) {
        int rm = i0 + wm * 32 + ma * 16 + gq;
#pragma unroll
        for (int na = 0; na < 2; na++) {
            int cn = j0 + wn * 16 + na * 8 + 2 * tg;
            *(float2*)(W + (size_t)rm * C_MID + cn) = make_float2(acc[ma][na][0], acc[ma][na][1]);
            *(float2*)(W + (size_t)(rm + 8) * C_MID + cn) = make_float2(acc[ma][na][2], acc[ma][na][3]);
        }
    }
    __syncthreads();
}

__device__ void afold2_body(int vx, int vy, int vz, char* smu,
                            const float* __restrict__ theta_b,
                            const float* __restrict__ out_b) {
    bf16* As = (bf16*)smu;                 // 64*136
    bf16* Bs = (bf16*)(smu + 17408);       // 2 * 64*136
    float* tbs = (float*)(smu + 52224);

    const int bz = vz;
    const int m0 = vy * 64;
    const int n0 = vx * 128;

    const int tid = threadIdx.x;
    const int lane = tid & 31, warp = tid >> 5;
    const int wm = warp >> 2, wn = warp & 3;
    const int gq = lane >> 2, tg = lane & 3;
    const int a_row = (lane & 7) + ((lane >> 3) & 1) * 8;
    const int a_col = (lane >> 4) * 8;
    const int bt_kr = (lane & 7) + ((lane >> 3) & 1) * 8;
    const int bt_nc = ((lane >> 4) & 1) * 8;

    const int brow = tid >> 2, bcb = (tid & 3) * 32;

#pragma unroll
    for (int h = 0; h < 2; h++) {
#pragma unroll
        for (int i = 0; i < 4; i++)
            cp16(&Bs[h * 8704 + brow * 136 + bcb + i * 8],
                 d_thw + (size_t)(h * 64 + brow) * C_IN + n0 + bcb + i * 8);
        CP_COMMIT();
    }

    if (tid < 128) tbs[tid] = theta_b[tid];

    {
        int arow = tid >> 2, acb = (tid & 3) * 32;
        const float* Wr = d_W + (size_t)bz * C_IN * C_MID + (size_t)(m0 + arow) * C_MID;
#pragma unroll
        for (int i = 0; i < 8; i++)
            *(uint2*)&As[arow * 136 + acb + i * 4] = f4_to_bf(*(const float4*)(Wr + acb + i * 4));
    }

    float acc[2][4][4] = {};
    CP_WAIT0();
    __syncthreads();

#pragma unroll
    for (int h = 0; h < 2; h++) {
#pragma unroll
        for (int kk2 = 0; kk2 < 64; kk2 += 16) {
            uint32_t a[2][4], bb[2][4];
#pragma unroll
            for (int ma = 0; ma < 2; ma++)
                ldsm4(a[ma], &As[(wm * 32 + ma * 16 + a_row) * 136 + h * 64 + kk2 + a_col]);
#pragma unroll
            for (int pr = 0; pr < 2; pr++)
                ldsm4t(bb[pr], &Bs[h * 8704 + (kk2 + bt_kr) * 136 + wn * 32 + pr * 16 + bt_nc]);
#pragma unroll
            for (int ma = 0; ma < 2; ma++)
#pragma unroll
                for (int na = 0; na < 4; na++)
                    mma_bf16(acc[ma][na], a[ma],
                             bb[na >> 1][(na & 1) * 2], bb[na >> 1][(na & 1) * 2 + 1]);
        }
    }

    bf16* Af = d_Af + (size_t)bz * C_IN * C_IN;
#pragma unroll
    for (int ma = 0; ma < 2; ma++) {
        int rm = m0 + wm * 32 + ma * 16 + gq;
#pragma unroll
        for (int na = 0; na < 4; na++) {
            int cn = n0 + wn * 32 + na * 8 + 2 * tg;
            *(bf162*)(Af + (size_t)rm * C_IN + cn) =
                __floats2bfloat162_rn(acc[ma][na][0] * INVN, acc[ma][na][1] * INVN);
            *(bf162*)(Af + (size_t)(rm + 8) * C_IN + cn) =
                __floats2bfloat162_rn(acc[ma][na][2] * INVN, acc[ma][na][3] * INVN);
        }
    }

    if (vx == 0) {
        int r = warp * 8;
#pragma unroll
        for (int d = 0; d < 8; d++) {
            uint2 w2 = *(const uint2*)&As[(r + d) * 136 + lane * 4];
            const bf162* pp = (const bf162*)&w2;
            float2 f0 = __bfloat1622float2(pp[0]);
            float2 f1 = __bfloat1622float2(pp[1]);
            float a = f0.x * tbs[lane * 4] + f0.y * tbs[lane * 4 + 1]
                    + f1.x * tbs[lane * 4 + 2] + f1.y * tbs[lane * 4 + 3];
#pragma unroll
            for (int o = 16; o; o >>= 1) a += __shfl_xor_sync(0xffffffffu, a, o);
            if (lane == 0) d_cvec[bz * C_IN + m0 + r + d] = a * INVN + out_b[m0 + r + d];
        }
    }
    __syncthreads();
}

__device__ void final_body(int vx, int vy, int vz, char* smu,
                           const float* __restrict__ x, float* __restrict__ out) {
    bf16* As = (bf16*)smu;                 // 3 * 64*40
    bf16* Bs = (bf16*)(smu + 15360);       // 3 * 32*136
    const int bz = vz;
    const int m0 = vy * 64;
    const int n0 = vx * 128;
    const bf16* A = d_Af + (size_t)bz * C_IN * C_IN;
    const bf16* Xb16 = d_Xbf + (size_t)bz * C_IN * NSP;
    const float* Xb = x + (size_t)bz * C_IN * NSP;
    float* Ob = out + (size_t)bz * C_IN * NSP;

    const int tid = threadIdx.x;
    const int lane = tid & 31, warp = tid >> 5;
    const int wm = warp >> 2, wn = warp & 3;
    const int gq = lane >> 2, tg = lane & 3;
    const int ar = tid >> 2, ac = (tid & 3) * 8;
    const int br = tid >> 3, bc = (tid & 7) * 8;
    const int a_row = (lane & 7) + ((lane >> 3) & 1) * 8;
    const int a_col = (lane >> 4) * 8;
    const int bt_kr = (lane & 7) + ((lane >> 3) & 1) * 8;
    const int bt_nc = ((lane >> 4) & 1) * 8;

    float acc[2][4][4] = {};

    auto issue = [&](int k0, int st) {
        cp16(&As[st * 2560 + ar * 40 + ac], A + (size_t)(m0 + ar) * C_IN + k0 + ac);
        cp16(&Bs[st * 4352 + br * 136 + bc], Xb16 + (size_t)(k0 + br) * NSP + n0 + bc);
        cp16(&Bs[st * 4352 + br * 136 + bc + 64], Xb16 + (size_t)(k0 + br) * NSP + n0 + bc + 64);
    };

    issue(0, 0); CP_COMMIT();
    issue(32, 1); CP_COMMIT();

    for (int i = 0; i < 8; i++) {
        CP_WAIT1();
        __syncthreads();
        int kn = (i + 2) * 32;
        if (kn < 256) issue(kn, (i + 2) % 3);
        CP_COMMIT();
        const int st = i % 3;
#pragma unroll
        for (int kk = 0; kk < 32; kk += 16) {
            uint32_t a[2][4], bb[2][4];
#pragma unroll
            for (int ma = 0; ma < 2; ma++)
                ldsm4(a[ma], &As[st * 2560 + (wm * 32 + ma * 16 + a_row) * 40 + kk + a_col]);
#pragma unroll
            for (int pr = 0; pr < 2; pr++)
                ldsm4t(bb[pr], &Bs[st * 4352 + (kk + bt_kr) * 136 + wn * 32 + pr * 16 + bt_nc]);
#pragma unroll
            for (int ma = 0; ma < 2; ma++)
#pragma unroll
                for (int na = 0; na < 4; na++)
                    mma_bf16(acc[ma][na], a[ma],
                             bb[na >> 1][(na & 1) * 2], bb[na >> 1][(na & 1) * 2 + 1]);
        }
    }

    const float* cb = d_cvec + bz * C_IN;
#pragma unroll
    for (int ma = 0; ma < 2; ma++) {
        int rm = m0 + wm * 32 + ma * 16 + gq;
        float c0 = cb[rm], c1 = cb[rm + 8];
#pragma unroll
        for (int na = 0; na < 4; na++) {
            int cn = n0 + wn * 32 + na * 8 + 2 * tg;
            float2 x0 = *(const float2*)(Xb + (size_t)rm * NSP + cn);
            float2 x1 = *(const float2*)(Xb + (size_t)(rm + 8) * NSP + cn);
            *(float2*)(Ob + (size_t)rm * NSP + cn) =
                make_float2(acc[ma][na][0] + x0.x + c0, acc[ma][na][1] + x0.y + c0);
            *(float2*)(Ob + (size_t)(rm + 8) * NSP + cn) =
                make_float2(acc[ma][na][2] + x1.x + c1, acc[ma][na][3] + x1.y + c1);
        }
    }
    __syncthreads();
}

// ---------------------------------------------------------------------------
// Persistent mega-kernel: 6 stages, 5 grid barriers
// ---------------------------------------------------------------------------
__global__ void __launch_bounds__(256, 2) mega(const float* __restrict__ x,
                                               const float* __restrict__ g_w,
                                               const float* __restrict__ g_b,
                                               const float* __restrict__ theta_w,
                                               const float* __restrict__ theta_b,
                                               const float* __restrict__ phi_w,
                                               const float* __restrict__ phi_b,
                                               const float* __restrict__ out_w,
                                               const float* __restrict__ out_b,
                                               float* __restrict__ out) {
    extern __shared__ char smu[];
    const int bid = blockIdx.x;

    // stage 0: convert + zero (297 virtual blocks)
    for (int v = bid; v < 297; v += GRIDN)
        conv_body(v, x, phi_w, g_w, theta_w, out_w);
    gbar(0);

    // stage 1: proj (256 tiles)
    for (int v = bid; v < 256; v += GRIDN)
        proj_body(v & 31, (v >> 5) & 1, v >> 6, smu);
    gbar(1);

    // stage 2: bsm (128 tiles)
    if (bid < 128)
        bsm_body(bid & 3, (bid >> 2) & 7, bid >> 5, smu);
    gbar(2);

    // stage 3: wfold (32 tiles)
    if (bid < 32)
        wfold_body(bid & 1, (bid >> 1) & 3, bid >> 3, smu, g_b, phi_b);
    gbar(3);

    // stage 4: afold2 (32 tiles)
    if (bid < 32)
        afold2_body(bid & 1, (bid >> 1) & 3, bid >> 3, smu, theta_b, out_b);
    gbar(4);

    // stage 5: final (512 tiles)
    for (int v = bid; v < 512; v += GRIDN)
        final_body(v & 31, (v >> 5) & 3, v >> 7, smu, x, out);
}

// ---------------------------------------------------------------------------
// Host launcher — 1 kernel
// ---------------------------------------------------------------------------
extern "C" void kernel_launch(void* const* d_in, const int* in_sizes, int n_in,
                              void* d_out, int out_size) {
    const float* x       = (const float*)d_in[0];
    const float* g_w     = (const float*)d_in[1];
    const float* g_b     = (const float*)d_in[2];
    const float* theta_w = (const float*)d_in[3];
    const float* theta_b = (const float*)d_in[4];
    const float* phi_w   = (const float*)d_in[5];
    const float* phi_b   = (const float*)d_in[6];
    const float* out_w   = (const float*)d_in[7];
    const float* out_b   = (const float*)d_in[8];
    float* out = (float*)d_out;

    static bool attr_set = false;
    if (!attr_set) {
        cudaFuncSetAttribute(mega, cudaFuncAttributeMaxDynamicSharedMemorySize, 57344);
        attr_set = true;
    }
    mega<<<GRIDN, 256, 57344>>>(x, g_w, g_b, theta_w, theta_b,
                                phi_w, phi_b, out_w, out_b, out);
}

// round 16
// speedup vs baseline: 1.0577x; 1.0577x over previous
#include <cuda_runtime.h>
#include <cuda_bf16.h>
#include <cstdint>

#define BATCH 4
#define C_IN 256
#define C_MID 128
#define NSP 4096
#define INVN (1.0f/4096.0f)
#define MIDG 128

typedef __nv_bfloat16 bf16;
typedef __nv_bfloat162 bf162;

// ---------------------------------------------------------------------------
// Device scratch
// ---------------------------------------------------------------------------
__device__ __align__(256) bf16  d_Xbf[BATCH * C_IN * NSP];
__device__ __align__(256) bf16  d_phw[C_MID * C_IN];
__device__ __align__(256) bf16  d_gw [C_MID * C_IN];
__device__ __align__(256) bf16  d_thw[C_MID * C_IN];
__device__ __align__(256) bf16  d_ow [C_IN * C_MID];
__device__ __align__(256) bf16  d_Tph[BATCH * C_MID * NSP];
__device__ __align__(256) bf16  d_Tg [BATCH * C_MID * NSP];
__device__ __align__(256) float d_M  [BATCH * C_MID * C_MID];
__device__ __align__(256) float d_gs [BATCH * C_MID];
__device__ __align__(256) float d_ws [BATCH * C_MID];
__device__ __align__(256) float d_W  [BATCH * C_IN * C_MID];
__device__ __align__(256) bf16  d_Af [BATCH * C_IN * C_IN];
__device__ __align__(256) float d_cvec[BATCH * C_IN];
__device__ unsigned int g_bc[4];

// ---------------------------------------------------------------------------
// Helpers
// ---------------------------------------------------------------------------
__device__ __forceinline__ void mma_bf16(float c[4], const uint32_t a[4],
                                         uint32_t b0, uint32_t b1) {
    asm volatile("mma.sync.aligned.m16n8k16.row.col.f32.bf16.bf16.f32 "
                 "{%0,%1,%2,%3}, {%4,%5,%6,%7}, {%8,%9}, {%0,%1,%2,%3};"
                 : "+f"(c[0]), "+f"(c[1]), "+f"(c[2]), "+f"(c[3])
                 : "r"(a[0]), "r"(a[1]), "r"(a[2]), "r"(a[3]), "r"(b0), "r"(b1));
}
__device__ __forceinline__ void ldsm4(uint32_t r[4], const bf16* p) {
    uint32_t addr = (uint32_t)__cvta_generic_to_shared(p);
    asm volatile("ldmatrix.sync.aligned.m8n8.x4.shared.b16 {%0,%1,%2,%3}, [%4];"
                 : "=r"(r[0]), "=r"(r[1]), "=r"(r[2]), "=r"(r[3]) : "r"(addr));
}
__device__ __forceinline__ void ldsm4t(uint32_t r[4], const bf16* p) {
    uint32_t addr = (uint32_t)__cvta_generic_to_shared(p);
    asm volatile("ldmatrix.sync.aligned.m8n8.x4.trans.shared.b16 {%0,%1,%2,%3}, [%4];"
                 : "=r"(r[0]), "=r"(r[1]), "=r"(r[2]), "=r"(r[3]) : "r"(addr));
}
__device__ __forceinline__ void cp16(bf16* s, const bf16* g) {
    uint32_t sa = (uint32_t)__cvta_generic_to_shared(s);
    asm volatile("cp.async.cg.shared.global [%0], [%1], 16;" :: "r"(sa), "l"(g));
}
#define CP_COMMIT() asm volatile("cp.async.commit_group;" ::: "memory")
#define CP_WAIT1()  asm volatile("cp.async.wait_group 1;" ::: "memory")
#define CP_WAIT0()  asm volatile("cp.async.wait_group 0;" ::: "memory")

__device__ __forceinline__ uint2 f4_to_bf(float4 v) {
    bf162 lo = __floats2bfloat162_rn(v.x, v.y);
    bf162 hi = __floats2bfloat162_rn(v.z, v.w);
    uint2 r;
    r.x = *(uint32_t*)&lo;
    r.y = *(uint32_t*)&hi;
    return r;
}
__device__ __forceinline__ float sum8bf(uint4 v) {
    const bf162* p = (const bf162*)&v;
    float s = 0.f;
#pragma unroll
    for (int i = 0; i < 4; i++) {
        float2 f = __bfloat1622float2(p[i]);
        s += f.x + f.y;
    }
    return s;
}

// epoch-based grid barrier over MIDG CTAs (monotonic; graph-replay safe)
__device__ __forceinline__ void gbar(int i) {
    __syncthreads();
    if (threadIdx.x == 0) {
        __threadfence();
        unsigned old = atomicAdd(&g_bc[i], 1u);
        unsigned goal = (old / MIDG + 1u) * MIDG;
        while (atomicAdd(&g_bc[i], 0u) < goal) __nanosleep(64);
        __threadfence();
    }
    __syncthreads();
}

// ---------------------------------------------------------------------------
// convert_init: x/phi_w/g_w/theta_w/out_w -> bf16, zero M/gs/ws. grid 297
// ---------------------------------------------------------------------------
__global__ void __launch_bounds__(256) convert_init(const float* __restrict__ x,
                                                    const float* __restrict__ phi_w,
                                                    const float* __restrict__ g_w,
                                                    const float* __restrict__ theta_w,
                                                    const float* __restrict__ out_w) {
    const int b = blockIdx.x, tid = threadIdx.x;
    if (b < 256) {
        const float4* src = (const float4*)x + (size_t)b * 4096;
        uint2* dst = (uint2*)d_Xbf + (size_t)b * 4096;
#pragma unroll 4
        for (int i = tid; i < 4096; i += 256) dst[i] = f4_to_bf(src[i]);
    } else if (b < 264) {
        const float4* src = (const float4*)phi_w + (b - 256) * 1024;
        uint2* dst = (uint2*)d_phw + (b - 256) * 1024;
#pragma unroll
        for (int i = tid; i < 1024; i += 256) dst[i] = f4_to_bf(src[i]);
    } else if (b < 272) {
        const float4* src = (const float4*)g_w + (b - 264) * 1024;
        uint2* dst = (uint2*)d_gw + (b - 264) * 1024;
#pragma unroll
        for (int i = tid; i < 1024; i += 256) dst[i] = f4_to_bf(src[i]);
    } else if (b < 280) {
        const float4* src = (const float4*)theta_w + (b - 272) * 1024;
        uint2* dst = (uint2*)d_thw + (b - 272) * 1024;
#pragma unroll
        for (int i = tid; i < 1024; i += 256) dst[i] = f4_to_bf(src[i]);
    } else if (b < 288) {
        const float4* src = (const float4*)out_w + (b - 280) * 1024;
        uint2* dst = (uint2*)d_ow + (b - 280) * 1024;
#pragma unroll
        for (int i = tid; i < 1024; i += 256) dst[i] = f4_to_bf(src[i]);
    } else if (b < 296) {
        float4* M4 = (float4*)d_M + (b - 288) * 2048;
        float4 z4 = make_float4(0, 0, 0, 0);
#pragma unroll
        for (int i = tid; i < 2048; i += 256) M4[i] = z4;
    } else {
        float4 z4 = make_float4(0, 0, 0, 0);
        if (tid < 128) {
            ((float4*)d_gs)[tid] = z4;
            ((float4*)d_ws)[tid] = z4;
        }
    }
}

// ---------------------------------------------------------------------------
// proj: Tph = phw @ Xbf, Tg = gw @ Xbf (bf16, cp.async 3-stage). grid (32,2,4)
// ---------------------------------------------------------------------------
__global__ void __launch_bounds__(256) proj() {
    __shared__ bf16 As1[3][64 * 40], As2[3][64 * 40], Bs[3][32 * 136];
    const int bz = blockIdx.z;
    const int m0 = blockIdx.y * 64;
    const int n0 = blockIdx.x * 128;
    const bf16* Xbf = d_Xbf + (size_t)bz * C_IN * NSP;

    const int tid = threadIdx.x;
    const int lane = tid & 31, warp = tid >> 5;
    const int wm = warp >> 2, wn = warp & 3;
    const int gq = lane >> 2, tg = lane & 3;
    const int ar = tid >> 2, ac = (tid & 3) * 8;
    const int br = tid >> 3, bc = (tid & 7) * 8;
    const int a_row = (lane & 7) + ((lane >> 3) & 1) * 8;
    const int a_col = (lane >> 4) * 8;
    const int bt_kr = (lane & 7) + ((lane >> 3) & 1) * 8;
    const int bt_nc = ((lane >> 4) & 1) * 8;

    float acc1[2][4][4] = {}, acc2[2][4][4] = {};

    auto issue = [&](int k0, int st) {
        cp16(&As1[st][ar * 40 + ac], d_phw + (size_t)(m0 + ar) * 256 + k0 + ac);
        cp16(&As2[st][ar * 40 + ac], d_gw + (size_t)(m0 + ar) * 256 + k0 + ac);
        cp16(&Bs[st][br * 136 + bc], Xbf + (size_t)(k0 + br) * NSP + n0 + bc);
        cp16(&Bs[st][br * 136 + bc + 64], Xbf + (size_t)(k0 + br) * NSP + n0 + bc + 64);
    };

    issue(0, 0); CP_COMMIT();
    issue(32, 1); CP_COMMIT();

    for (int i = 0; i < 8; i++) {
        CP_WAIT1();
        __syncthreads();
        int kn = (i + 2) * 32;
        if (kn < 256) issue(kn, (i + 2) % 3);
        CP_COMMIT();
        const int st = i % 3;
#pragma unroll
        for (int kk = 0; kk < 32; kk += 16) {
            uint32_t a1[2][4], a2[2][4], bb[2][4];
#pragma unroll
            for (int ma = 0; ma < 2; ma++) {
                int rb = wm * 32 + ma * 16;
                ldsm4(a1[ma], &As1[st][(rb + a_row) * 40 + kk + a_col]);
                ldsm4(a2[ma], &As2[st][(rb + a_row) * 40 + kk + a_col]);
            }
#pragma unroll
            for (int pr = 0; pr < 2; pr++)
                ldsm4t(bb[pr], &Bs[st][(kk + bt_kr) * 136 + wn * 32 + pr * 16 + bt_nc]);
#pragma unroll
            for (int ma = 0; ma < 2; ma++)
#pragma unroll
                for (int na = 0; na < 4; na++) {
                    uint32_t b0 = bb[na >> 1][(na & 1) * 2];
                    uint32_t b1 = bb[na >> 1][(na & 1) * 2 + 1];
                    mma_bf16(acc1[ma][na], a1[ma], b0, b1);
                    mma_bf16(acc2[ma][na], a2[ma], b0, b1);
                }
        }
    }

    bf16* C1 = d_Tph + (size_t)bz * C_MID * NSP;
    bf16* C2 = d_Tg + (size_t)bz * C_MID * NSP;
#pragma unroll
    for (int ma = 0; ma < 2; ma++) {
        int rm = m0 + wm * 32 + ma * 16 + gq;
#pragma unroll
        for (int na = 0; na < 4; na++) {
            int cn = n0 + wn * 32 + na * 8 + 2 * tg;
            *(bf162*)(C1 + (size_t)rm * NSP + cn) =
                __floats2bfloat162_rn(acc1[ma][na][0], acc1[ma][na][1]);
            *(bf162*)(C1 + (size_t)(rm + 8) * NSP + cn) =
                __floats2bfloat162_rn(acc1[ma][na][2], acc1[ma][na][3]);
            *(bf162*)(C2 + (size_t)rm * NSP + cn) =
                __floats2bfloat162_rn(acc2[ma][na][0], acc2[ma][na][1]);
            *(bf162*)(C2 + (size_t)(rm + 8) * NSP + cn) =
                __floats2bfloat162_rn(acc2[ma][na][2], acc2[ma][na][3]);
        }
    }
}

// ---------------------------------------------------------------------------
// mid_mega stage bodies
// ---------------------------------------------------------------------------
__device__ void bsm_body(int vx, int vy, int vz, char* smu) {
    bf16* As = (bf16*)smu;
    bf16* Bs = (bf16*)(smu + 15360);
    const int ti = vx >> 1, tj = vx & 1;
    const int i0 = ti * 64, j0 = tj * 64;
    const int kb = vy * 512;
    const int bz = vz;
    const bf16* A = d_Tg + (size_t)bz * C_MID * NSP;
    const bf16* B = d_Tph + (size_t)bz * C_MID * NSP;

    const int tid = threadIdx.x;
    const int lane = tid & 31, warp = tid >> 5;
    const int wm = warp >> 2, wn = warp & 3;
    const int gq = lane >> 2, tg = lane & 3;
    const int lr = tid >> 2, lc = (tid & 3) * 8;
    const int a_row = (lane & 7) + ((lane >> 3) & 1) * 8;
    const int a_col = (lane >> 4) * 8;
    const int b_nr = (lane & 7) + ((lane >> 4) & 1) * 8;
    const int b_kc = ((lane >> 3) & 1) * 8;

    float acc[2][2][4] = {};
    float sa = 0.f, sb = 0.f;
    const bool dosum = (ti == tj);

    auto issue = [&](int k0, int st) {
        cp16(&As[st * 2560 + lr * 40 + lc], A + (size_t)(i0 + lr) * NSP + kb + k0 + lc);
        cp16(&Bs[st * 2560 + lr * 40 + lc], B + (size_t)(j0 + lr) * NSP + kb + k0 + lc);
    };

    issue(0, 0); CP_COMMIT();
    issue(32, 1); CP_COMMIT();

    for (int i = 0; i < 16; i++) {
        CP_WAIT1();
        __syncthreads();
        int kn = (i + 2) * 32;
        if (kn < 512) issue(kn, (i + 2) % 3);
        CP_COMMIT();
        const int st = i % 3;
        if (dosum) {
            sa += sum8bf(*(const uint4*)&As[st * 2560 + lr * 40 + lc]);
            sb += sum8bf(*(const uint4*)&Bs[st * 2560 + lr * 40 + lc]);
        }
#pragma unroll
        for (int kk = 0; kk < 32; kk += 16) {
            uint32_t a[2][4], bbv[4];
#pragma unroll
            for (int ma = 0; ma < 2; ma++)
                ldsm4(a[ma], &As[st * 2560 + (wm * 32 + ma * 16 + a_row) * 40 + kk + a_col]);
            ldsm4(bbv, &Bs[st * 2560 + (wn * 16 + b_nr) * 40 + kk + b_kc]);
#pragma unroll
            for (int ma = 0; ma < 2; ma++) {
                mma_bf16(acc[ma][0], a[ma], bbv[0], bbv[1]);
                mma_bf16(acc[ma][1], a[ma], bbv[2], bbv[3]);
            }
        }
    }

    float* Mp = d_M + (size_t)bz * C_MID * C_MID;
#pragma unroll
    for (int ma = 0; ma < 2; ma++) {
        int rr = i0 + wm * 32 + ma * 16 + gq;
#pragma unroll
        for (int na = 0; na < 2; na++) {
            int cn = j0 + wn * 16 + na * 8 + 2 * tg;
            atomicAdd(&Mp[(size_t)rr * C_MID + cn],           acc[ma][na][0]);
            atomicAdd(&Mp[(size_t)rr * C_MID + cn + 1],       acc[ma][na][1]);
            atomicAdd(&Mp[(size_t)(rr + 8) * C_MID + cn],     acc[ma][na][2]);
            atomicAdd(&Mp[(size_t)(rr + 8) * C_MID + cn + 1], acc[ma][na][3]);
        }
    }
    if (dosum) {
        sa += __shfl_xor_sync(0xffffffffu, sa, 1);
        sa += __shfl_xor_sync(0xffffffffu, sa, 2);
        sb += __shfl_xor_sync(0xffffffffu, sb, 1);
        sb += __shfl_xor_sync(0xffffffffu, sb, 2);
        if ((tid & 3) == 0) {
            atomicAdd(&d_gs[bz * C_MID + i0 + lr], sa);
            atomicAdd(&d_ws[bz * C_MID + j0 + lr], sb);
        }
    }
    __syncthreads();
}

__device__ void wfold_body(int vx, int vy, int vz, char* smu,
                           const float* __restrict__ g_b,
                           const float* __restrict__ phi_b) {
    bf16* As = (bf16*)smu;
    bf16* Bs = (bf16*)(smu + 17408);
    float* pbs = (float*)(smu + 35840);
    float* wss = (float*)(smu + 36352);

    const int bz = vz;
    const int i0 = vy * 64;
    const int j0 = vx * 64;

    const int tid = threadIdx.x;
    const int lane = tid & 31, warp = tid >> 5;
    const int wm = warp >> 2, wn = warp & 3;
    const int gq = lane >> 2, tg = lane & 3;
    const int a_row = (lane & 7) + ((lane >> 3) & 1) * 8;
    const int a_col = (lane >> 4) * 8;
    const int bt_kr = (lane & 7) + ((lane >> 3) & 1) * 8;
    const int bt_nc = ((lane >> 4) & 1) * 8;

    {
        int arow = tid >> 2, acb = (tid & 3) * 32;
#pragma unroll
        for (int i = 0; i < 4; i++)
            cp16(&As[arow * 136 + acb + i * 8],
                 d_ow + (size_t)(i0 + arow) * C_MID + acb + i * 8);
        CP_COMMIT();
    }

    if (tid < 128) {
        pbs[tid] = phi_b[tid];
        wss[tid] = d_ws[bz * C_MID + tid];
    }
    __syncthreads();

    {
        int brow = tid >> 1, bcb = (tid & 1) * 32;
        const float gsv = d_gs[bz * C_MID + brow];
        const float gbv = g_b[brow];
        const float* Mrow = d_M + (size_t)bz * C_MID * C_MID + (size_t)brow * C_MID + j0;
#pragma unroll
        for (int i = 0; i < 8; i++) {
            int c = bcb + i * 4;
            float4 mr = *(const float4*)(Mrow + c);
            float4 pb = *(const float4*)&pbs[j0 + c];
            float4 wv = *(const float4*)&wss[j0 + c];
            float4 v;
            v.x = mr.x + gsv * pb.x + gbv * (wv.x + 4096.f * pb.x);
            v.y = mr.y + gsv * pb.y + gbv * (wv.y + 4096.f * pb.y);
            v.z = mr.z + gsv * pb.z + gbv * (wv.z + 4096.f * pb.z);
            v.w = mr.w + gsv * pb.w + gbv * (wv.w + 4096.f * pb.w);
            *(uint2*)&Bs[brow * 72 + c] = f4_to_bf(v);
        }
    }
    CP_WAIT0();
    __syncthreads();

    float acc[2][2][4] = {};
#pragma unroll
    for (int kk = 0; kk < 128; kk += 16) {
        uint32_t a[2][4], bb[4];
#pragma unroll
        for (int ma = 0; ma < 2; ma++)
            ldsm4(a[ma], &As[(wm * 32 + ma * 16 + a_row) * 136 + kk + a_col]);
        ldsm4t(bb, &Bs[(kk + bt_kr) * 72 + wn * 16 + bt_nc]);
#pragma unroll
        for (int ma = 0; ma < 2; ma++) {
            mma_bf16(acc[ma][0], a[ma], bb[0], bb[1]);
            mma_bf16(acc[ma][1], a[ma], bb[2], bb[3]);
        }
    }

    float* W = d_W + (size_t)bz * C_IN * C_MID;
#pragma unroll
    for (int ma = 0; ma < 2; ma++) {
        int rm = i0 + wm * 32 + ma * 16 + gq;
#pragma unroll
        for (int na = 0; na < 2; na++) {
            int cn = j0 + wn * 16 + na * 8 + 2 * tg;
            *(float2*)(W + (size_t)rm * C_MID + cn) = make_float2(acc[ma][na][0], acc[ma][na][1]);
            *(float2*)(W + (size_t)(rm + 8) * C_MID + cn) = make_float2(acc[ma][na][2], acc[ma][na][3]);
        }
    }
    __syncthreads();
}

__device__ void afold2_body(int vx, int vy, int vz, char* smu,
                            const float* __restrict__ theta_b,
                            const float* __restrict__ out_b) {
    bf16* As = (bf16*)smu;
    bf16* Bs = (bf16*)(smu + 17408);
    float* tbs = (float*)(smu + 52224);

    const int bz = vz;
    const int m0 = vy * 64;
    const int n0 = vx * 128;

    const int tid = threadIdx.x;
    const int lane = tid & 31, warp = tid >> 5;
    const int wm = warp >> 2, wn = warp & 3;
    const int gq = lane >> 2, tg = lane & 3;
    const int a_row = (lane & 7) + ((lane >> 3) & 1) * 8;
    const int a_col = (lane >> 4) * 8;
    const int bt_kr = (lane & 7) + ((lane >> 3) & 1) * 8;
    const int bt_nc = ((lane >> 4) & 1) * 8;

    const int brow = tid >> 2, bcb = (tid & 3) * 32;

#pragma unroll
    for (int h = 0; h < 2; h++) {
#pragma unroll
        for (int i = 0; i < 4; i++)
            cp16(&Bs[h * 8704 + brow * 136 + bcb + i * 8],
                 d_thw + (size_t)(h * 64 + brow) * C_IN + n0 + bcb + i * 8);
        CP_COMMIT();
    }

    if (tid < 128) tbs[tid] = theta_b[tid];

    {
        int arow = tid >> 2, acb = (tid & 3) * 32;
        const float* Wr = d_W + (size_t)bz * C_IN * C_MID + (size_t)(m0 + arow) * C_MID;
#pragma unroll
        for (int i = 0; i < 8; i++)
            *(uint2*)&As[arow * 136 + acb + i * 4] = f4_to_bf(*(const float4*)(Wr + acb + i * 4));
    }

    float acc[2][4][4] = {};
    CP_WAIT0();
    __syncthreads();

#pragma unroll
    for (int h = 0; h < 2; h++) {
#pragma unroll
        for (int kk2 = 0; kk2 < 64; kk2 += 16) {
            uint32_t a[2][4], bb[2][4];
#pragma unroll
            for (int ma = 0; ma < 2; ma++)
                ldsm4(a[ma], &As[(wm * 32 + ma * 16 + a_row) * 136 + h * 64 + kk2 + a_col]);
#pragma unroll
            for (int pr = 0; pr < 2; pr++)
                ldsm4t(bb[pr], &Bs[h * 8704 + (kk2 + bt_kr) * 136 + wn * 32 + pr * 16 + bt_nc]);
#pragma unroll
            for (int ma = 0; ma < 2; ma++)
#pragma unroll
                for (int na = 0; na < 4; na++)
                    mma_bf16(acc[ma][na], a[ma],
                             bb[na >> 1][(na & 1) * 2], bb[na >> 1][(na & 1) * 2 + 1]);
        }
    }

    bf16* Af = d_Af + (size_t)bz * C_IN * C_IN;
#pragma unroll
    for (int ma = 0; ma < 2; ma++) {
        int rm = m0 + wm * 32 + ma * 16 + gq;
#pragma unroll
        for (int na = 0; na < 4; na++) {
            int cn = n0 + wn * 32 + na * 8 + 2 * tg;
            *(bf162*)(Af + (size_t)rm * C_IN + cn) =
                __floats2bfloat162_rn(acc[ma][na][0] * INVN, acc[ma][na][1] * INVN);
            *(bf162*)(Af + (size_t)(rm + 8) * C_IN + cn) =
                __floats2bfloat162_rn(acc[ma][na][2] * INVN, acc[ma][na][3] * INVN);
        }
    }

    if (vx == 0) {
        int r = warp * 8;
#pragma unroll
        for (int d = 0; d < 8; d++) {
            uint2 w2 = *(const uint2*)&As[(r + d) * 136 + lane * 4];
            const bf162* pp = (const bf162*)&w2;
            float2 f0 = __bfloat1622float2(pp[0]);
            float2 f1 = __bfloat1622float2(pp[1]);
            float a = f0.x * tbs[lane * 4] + f0.y * tbs[lane * 4 + 1]
                    + f1.x * tbs[lane * 4 + 2] + f1.y * tbs[lane * 4 + 3];
#pragma unroll
            for (int o = 16; o; o >>= 1) a += __shfl_xor_sync(0xffffffffu, a, o);
            if (lane == 0) d_cvec[bz * C_IN + m0 + r + d] = a * INVN + out_b[m0 + r + d];
        }
    }
    __syncthreads();
}

// ---------------------------------------------------------------------------
// mid_mega: bsm -> gbar -> wfold -> gbar -> afold2, grid 128
// ---------------------------------------------------------------------------
__global__ void __launch_bounds__(256, 1) mid_mega(const float* __restrict__ g_b,
                                                   const float* __restrict__ phi_b,
                                                   const float* __restrict__ theta_b,
                                                   const float* __restrict__ out_b) {
    extern __shared__ char smu[];
    const int bid = blockIdx.x;

    bsm_body(bid & 3, (bid >> 2) & 7, bid >> 5, smu);
    gbar(0);
    if (bid < 32)
        wfold_body(bid & 1, (bid >> 1) & 3, bid >> 3, smu, g_b, phi_b);
    gbar(1);
    if (bid < 32)
        afold2_body(bid & 1, (bid >> 1) & 3, bid >> 3, smu, theta_b, out_b);
}

// ---------------------------------------------------------------------------
// final: out = Af @ Xbf + X + cvec  (bf16, cp.async 3-stage). grid (32, 4, 4)
// ---------------------------------------------------------------------------
__global__ void __launch_bounds__(256) final_k(const float* __restrict__ x,
                                               float* __restrict__ out) {
    __shared__ bf16 As[3][64 * 40], Bs[3][32 * 136];
    const int bz = blockIdx.z;
    const int m0 = blockIdx.y * 64;
    const int n0 = blockIdx.x * 128;
    const bf16* A = d_Af + (size_t)bz * C_IN * C_IN;
    const bf16* Xb16 = d_Xbf + (size_t)bz * C_IN * NSP;
    const float* Xb = x + (size_t)bz * C_IN * NSP;
    float* Ob = out + (size_t)bz * C_IN * NSP;

    const int tid = threadIdx.x;
    const int lane = tid & 31, warp = tid >> 5;
    const int wm = warp >> 2, wn = warp & 3;
    const int gq = lane >> 2, tg = lane & 3;
    const int ar = tid >> 2, ac = (tid & 3) * 8;
    const int br = tid >> 3, bc = (tid & 7) * 8;
    const int a_row = (lane & 7) + ((lane >> 3) & 1) * 8;
    const int a_col = (lane >> 4) * 8;
    const int bt_kr = (lane & 7) + ((lane >> 3) & 1) * 8;
    const int bt_nc = ((lane >> 4) & 1) * 8;

    float acc[2][4][4] = {};

    auto issue = [&](int k0, int st) {
        cp16(&As[st][ar * 40 + ac], A + (size_t)(m0 + ar) * C_IN + k0 + ac);
        cp16(&Bs[st][br * 136 + bc], Xb16 + (size_t)(k0 + br) * NSP + n0 + bc);
        cp16(&Bs[st][br * 136 + bc + 64], Xb16 + (size_t)(k0 + br) * NSP + n0 + bc + 64);
    };

    issue(0, 0); CP_COMMIT();
    issue(32, 1); CP_COMMIT();

    for (int i = 0; i < 8; i++) {
        CP_WAIT1();
        __syncthreads();
        int kn = (i + 2) * 32;
        if (kn < 256) issue(kn, (i + 2) % 3);
        CP_COMMIT();
        const int st = i % 3;
#pragma unroll
        for (int kk = 0; kk < 32; kk += 16) {
            uint32_t a[2][4], bb[2][4];
#pragma unroll
            for (int ma = 0; ma < 2; ma++)
                ldsm4(a[ma], &As[st][(wm * 32 + ma * 16 + a_row) * 40 + kk + a_col]);
#pragma unroll
            for (int pr = 0; pr < 2; pr++)
                ldsm4t(bb[pr], &Bs[st][(kk + bt_kr) * 136 + wn * 32 + pr * 16 + bt_nc]);
#pragma unroll
            for (int ma = 0; ma < 2; ma++)
#pragma unroll
                for (int na = 0; na < 4; na++)
                    mma_bf16(acc[ma][na], a[ma],
                             bb[na >> 1][(na & 1) * 2], bb[na >> 1][(na & 1) * 2 + 1]);
        }
    }

    const float* cb = d_cvec + bz * C_IN;
#pragma unroll
    for (int ma = 0; ma < 2; ma++) {
        int rm = m0 + wm * 32 + ma * 16 + gq;
        float c0 = cb[rm], c1 = cb[rm + 8];
#pragma unroll
        for (int na = 0; na < 4; na++) {
            int cn = n0 + wn * 32 + na * 8 + 2 * tg;
            float2 x0 = *(const float2*)(Xb + (size_t)rm * NSP + cn);
            float2 x1 = *(const float2*)(Xb + (size_t)(rm + 8) * NSP + cn);
            *(float2*)(Ob + (size_t)rm * NSP + cn) =
                make_float2(acc[ma][na][0] + x0.x + c0, acc[ma][na][1] + x0.y + c0);
            *(float2*)(Ob + (size_t)(rm + 8) * NSP + cn) =
                make_float2(acc[ma][na][2] + x1.x + c1, acc[ma][na][3] + x1.y + c1);
        }
    }
}

// ---------------------------------------------------------------------------
// Host launcher — 4 kernels
// ---------------------------------------------------------------------------
extern "C" void kernel_launch(void* const* d_in, const int* in_sizes, int n_in,
                              void* d_out, int out_size) {
    const float* x       = (const float*)d_in[0];
    const float* g_w     = (const float*)d_in[1];
    const float* g_b     = (const float*)d_in[2];
    const float* theta_w = (const float*)d_in[3];
    const float* theta_b = (const float*)d_in[4];
    const float* phi_w   = (const float*)d_in[5];
    const float* phi_b   = (const float*)d_in[6];
    const float* out_w   = (const float*)d_in[7];
    const float* out_b   = (const float*)d_in[8];
    float* out = (float*)d_out;

    static bool attr_set = false;
    if (!attr_set) {
        cudaFuncSetAttribute(mid_mega, cudaFuncAttributeMaxDynamicSharedMemorySize, 53248);
        attr_set = true;
    }

    convert_init<<<297, 256>>>(x, phi_w, g_w, theta_w, out_w);
    proj<<<dim3(32, 2, 4), 256>>>();
    mid_mega<<<MIDG, 256, 53248>>>(g_b, phi_b, theta_b, out_b);
    final_k<<<dim3(32, 4, 4), 256>>>(x, out);
}